// round 6
// baseline (speedup 1.0000x reference)
#include <cuda_runtime.h>
#include <cuda_bf16.h>
#include <math.h>
#include <cstdint>

#define NN 50000
#define EE 800000
#define GG 512
#define HH 128
#define LL 3
#define OUTC 10
#define NHTOT (NN * HH)
#define HSQ (HH * HH)
#define NB ((NN + 255) / 256)
#define KBIG 512
#define NP 50176

// ---------------- scratch (device globals) ----------------------------------
__device__ float  d_bufA[NHTOT];
__device__ float  d_bufB[NHTOT];
__device__ float  d_kc[NN];
__device__ float  d_rs[NN];
__device__ float  d_rdeg[NN];
__device__ int    d_rp[NN + 1];
__device__ int    d_cnt[NN];
__device__ int    d_bsum[NB];
__device__ int    d_colsrc[EE];
__device__ float  d_reps[(LL + 1) * GG * HH];
__device__ __nv_bfloat16 d_hhi[NP * HH], d_hlo[NP * HH];   // h (or x) split
__device__ __nv_bfloat16 d_shi[NP * HH], d_slo[NP * HH];   // s_agg split
__device__ __nv_bfloat16 d_ghi[NP * HH], d_glo[NP * HH];   // g_agg split
__device__ __nv_bfloat16 d_Bchi[KBIG * HH];                // combined B [n][k] hi
__device__ __nv_bfloat16 d_Bclo[KBIG * HH];
__device__ __nv_bfloat16 d_B1hi[HSQ];
__device__ __nv_bfloat16 d_B1lo[HSQ];
__device__ int    d_gs[GG + 1];
__device__ float  d_naa[LL * 4];
__device__ float  d_pa[LL * 3];
__device__ float  d_roa[(LL + 1) * 3];
__device__ float  d_laa[3];
__device__ double d_stats[2];

__device__ __forceinline__ float eluf(float x) { return x > 0.f ? x : expm1f(x); }

__device__ __forceinline__ uint32_t smem_u32(const void* p) {
    uint32_t a;
    asm("{ .reg .u64 t; cvta.to.shared.u64 t, %1; cvt.u32.u64 %0, t; }" : "=r"(a) : "l"(p));
    return a;
}

__device__ __forceinline__ void ldm_x4(uint32_t r[4], uint32_t addr) {
    asm volatile("ldmatrix.sync.aligned.m8n8.x4.shared.b16 {%0,%1,%2,%3}, [%4];"
                 : "=r"(r[0]), "=r"(r[1]), "=r"(r[2]), "=r"(r[3]) : "r"(addr));
}

__device__ __forceinline__ void mma_bf16(float c[4], const uint32_t a[4],
                                         uint32_t b0, uint32_t b1) {
    asm volatile(
        "mma.sync.aligned.m16n8k16.row.col.f32.bf16.bf16.f32 "
        "{%0,%1,%2,%3},{%4,%5,%6,%7},{%8,%9},{%0,%1,%2,%3};"
        : "+f"(c[0]), "+f"(c[1]), "+f"(c[2]), "+f"(c[3])
        : "r"(a[0]), "r"(a[1]), "r"(a[2]), "r"(a[3]), "r"(b0), "r"(b1));
}

#define CP_ASYNC16(dst, src) asm volatile("cp.async.cg.shared.global [%0], [%1], 16;" :: "r"(dst), "l"(src))
#define CP_COMMIT()          asm volatile("cp.async.commit_group;")
#define CP_WAIT(n)           asm volatile("cp.async.wait_group %0;" :: "n"(n))

__device__ __forceinline__ uint32_t swzoff(int row, int col) {
    return (uint32_t)(row * 128 + ((((col >> 3) ^ (row & 7))) << 4));
}

__device__ __forceinline__ void split_store4(__nv_bfloat16* hi, __nv_bfloat16* lo,
                                             size_t idx, float4 v) {
    __nv_bfloat162 h0 = __floats2bfloat162_rn(v.x, v.y);
    __nv_bfloat162 h1 = __floats2bfloat162_rn(v.z, v.w);
    float2 f0 = __bfloat1622float2(h0), f1 = __bfloat1622float2(h1);
    *(__nv_bfloat162*)&hi[idx]     = h0;
    *(__nv_bfloat162*)&hi[idx + 2] = h1;
    *(__nv_bfloat162*)&lo[idx]     = __floats2bfloat162_rn(v.x - f0.x, v.y - f0.y);
    *(__nv_bfloat162*)&lo[idx + 2] = __floats2bfloat162_rn(v.z - f1.x, v.w - f1.y);
}

#define STG_SZ  65536
#define OFF_ALO 16384
#define OFF_BHI 32768
#define OFF_BLO 49152
#define SM_TOTAL 131072

__device__ __forceinline__ void load_stage(
    uint32_t base, const __nv_bfloat16* ah, const __nv_bfloat16* al,
    const __nv_bfloat16* bh, const __nv_bfloat16* bl, int lrow, int lcol) {
#pragma unroll
    for (int j = 0; j < 4; j++) {
        uint32_t d = swzoff(lrow, lcol + j * 8);
        CP_ASYNC16(base + d,           ah + j * 8);
        CP_ASYNC16(base + OFF_ALO + d, al + j * 8);
        CP_ASYNC16(base + OFF_BHI + d, bh + j * 8);
        CP_ASYNC16(base + OFF_BLO + d, bl + j * 8);
    }
    CP_COMMIT();
}

__device__ __forceinline__ void compute_slice(float (&acc)[4][4][4], uint32_t base,
                                              int m_base, int n_base, int lane) {
    int lr = lane & 15, lg2 = (lane >> 4) * 8;
#pragma unroll
    for (int ks = 0; ks < 4; ks++) {
        int k0 = ks * 16;
        uint32_t ah[4][4], al[4][4];
#pragma unroll
        for (int mt = 0; mt < 4; mt++) {
            int row = m_base + mt * 16 + lr;
            ldm_x4(ah[mt], base + swzoff(row, k0 + lg2));
            ldm_x4(al[mt], base + OFF_ALO + swzoff(row, k0 + lg2));
        }
        uint32_t bhm[2][4], blm[2][4];
#pragma unroll
        for (int np = 0; np < 2; np++) {
            int row = n_base + np * 16 + lr;
            ldm_x4(bhm[np], base + OFF_BHI + swzoff(row, k0 + lg2));
            ldm_x4(blm[np], base + OFF_BLO + swzoff(row, k0 + lg2));
        }
#pragma unroll
        for (int mt = 0; mt < 4; mt++)
#pragma unroll
            for (int nt = 0; nt < 4; nt++) {
                int np = nt >> 1, sel = nt & 1;
                uint32_t b0h = sel ? bhm[np][1] : bhm[np][0];
                uint32_t b1h = sel ? bhm[np][3] : bhm[np][2];
                uint32_t b0l = sel ? blm[np][1] : blm[np][0];
                uint32_t b1l = sel ? blm[np][3] : blm[np][2];
                mma_bf16(acc[mt][nt], ah[mt], b0h, b1h);
                mma_bf16(acc[mt][nt], al[mt], b0h, b1h);
                mma_bf16(acc[mt][nt], ah[mt], b0l, b1l);
            }
    }
}

// ---------------- tensor-core GEMM ------------------------------------------
// MODE 0 (NSLICES=2): C = x @ B1, epilogue bias+elu, writes C + split Chi/Clo
// MODE 1 (NSLICES=8): C = elu(h@Wh + s@Wu + rdeg.(s@Wv) + g@Wg), + LN stats
// chunks: 0->a0(h), 1->a1(s), 2->a1(s, separate acc, rdeg in epilogue), 3->a3(g)
template <int NSLICES, int MODE>
__global__ void __launch_bounds__(256, 1) gemm_mma(
    const __nv_bfloat16* __restrict__ a0h, const __nv_bfloat16* __restrict__ a0l,
    const __nv_bfloat16* __restrict__ a1h, const __nv_bfloat16* __restrict__ a1l,
    const __nv_bfloat16* __restrict__ a3h, const __nv_bfloat16* __restrict__ a3l,
    const __nv_bfloat16* __restrict__ Bh, const __nv_bfloat16* __restrict__ Bl,
    float* __restrict__ C, __nv_bfloat16* __restrict__ Chi, __nv_bfloat16* __restrict__ Clo,
    const float* __restrict__ bias, const float* __restrict__ rdeg) {
    extern __shared__ char smem[];
    uint32_t sb = smem_u32(smem);
    const int tid = threadIdx.x;
    const int wid = tid >> 5, lane = tid & 31;
    const int warp_m = wid & 1, warp_n = wid >> 1;
    const int bm = blockIdx.x * 128;
    const int KB = NSLICES * 64;

    const int lrow = tid >> 1;
    const int lcol = (tid & 1) * 32;
    const size_t arow = (size_t)(bm + lrow) * HH;
    const size_t brow = (size_t)lrow * KB;

    float acc[4][4][4];
    float acc2[4][4][4];
#pragma unroll
    for (int i = 0; i < 4; i++)
#pragma unroll
        for (int j = 0; j < 4; j++)
#pragma unroll
            for (int q = 0; q < 4; q++) { acc[i][j][q] = 0.f; if (MODE == 1) acc2[i][j][q] = 0.f; }

    const int m_base = warp_m * 64;
    const int n_base = warp_n * 32;

    load_stage(sb, a0h + arow + lcol, a0l + arow + lcol,
               Bh + brow + lcol, Bl + brow + lcol, lrow, lcol);

#pragma unroll
    for (int s = 0; s < NSLICES; s++) {
        if (s + 1 < NSLICES) {
            const int sn = s + 1;
            const int chunk = sn >> 1, koff = (sn & 1) * 64;
            const __nv_bfloat16* ah = (chunk == 0) ? a0h : (chunk == 3) ? a3h : a1h;
            const __nv_bfloat16* al = (chunk == 0) ? a0l : (chunk == 3) ? a3l : a1l;
            load_stage(sb + (sn & 1) * STG_SZ,
                       ah + arow + koff + lcol, al + arow + koff + lcol,
                       Bh + brow + sn * 64 + lcol, Bl + brow + sn * 64 + lcol,
                       lrow, lcol);
            CP_WAIT(1);
        } else {
            CP_WAIT(0);
        }
        __syncthreads();
        uint32_t base = sb + (s & 1) * STG_SZ;
        if (MODE == 1 && (s >> 1) == 2)
            compute_slice(acc2, base, m_base, n_base, lane);
        else
            compute_slice(acc, base, m_base, n_base, lane);
        __syncthreads();
    }

    // ---- epilogue
    float lsum = 0.f, lsq = 0.f;
    int rq = lane >> 2, cq = (lane & 3) * 2;
#pragma unroll
    for (int mt = 0; mt < 4; mt++) {
#pragma unroll
        for (int half = 0; half < 2; half++) {
            int gm = bm + m_base + mt * 16 + rq + half * 8;
            if (gm >= NN) continue;
            float rd = (MODE == 1) ? rdeg[gm] : 0.f;
#pragma unroll
            for (int nt = 0; nt < 4; nt++) {
                int col = n_base + nt * 8 + cq;
                float v0 = acc[mt][nt][half * 2];
                float v1 = acc[mt][nt][half * 2 + 1];
                if (MODE == 0) {
                    v0 = eluf(v0 + bias[col]);
                    v1 = eluf(v1 + bias[col + 1]);
                    __nv_bfloat162 h = __floats2bfloat162_rn(v0, v1);
                    float2 hf = __bfloat1622float2(h);
                    *(__nv_bfloat162*)&Chi[(size_t)gm * HH + col] = h;
                    *(__nv_bfloat162*)&Clo[(size_t)gm * HH + col] =
                        __floats2bfloat162_rn(v0 - hf.x, v1 - hf.y);
                } else {
                    v0 = eluf(fmaf(rd, acc2[mt][nt][half * 2], v0));
                    v1 = eluf(fmaf(rd, acc2[mt][nt][half * 2 + 1], v1));
                    lsum += v0 + v1;
                    lsq = fmaf(v0, v0, lsq); lsq = fmaf(v1, v1, lsq);
                }
                *(float2*)&C[(size_t)gm * HH + col] = make_float2(v0, v1);
            }
        }
    }
    if (MODE == 1) {
        double ds = (double)lsum, dq = (double)lsq;
#pragma unroll
        for (int o = 16; o; o >>= 1) {
            ds += __shfl_down_sync(0xffffffffu, ds, o);
            dq += __shfl_down_sync(0xffffffffu, dq, o);
        }
        __shared__ double ssum[8], ssq[8];
        if (lane == 0) { ssum[wid] = ds; ssq[wid] = dq; }
        __syncthreads();
        if (tid == 0) {
            double a = 0.0, b = 0.0;
#pragma unroll
            for (int i = 0; i < 8; i++) { a += ssum[i]; b += ssq[i]; }
            atomicAdd(&d_stats[0], a);
            atomicAdd(&d_stats[1], b);
        }
    }
}

// ---------------- setup: graph starts + softmaxes + node init ---------------
__device__ void softmax_n(const float* in, float* out, int n) {
    float m = in[0];
    for (int i = 1; i < n; i++) m = fmaxf(m, in[i]);
    float s = 0.f;
    for (int i = 0; i < n; i++) { out[i] = expf(in[i] - m); s += out[i]; }
    float inv = 1.f / s;
    for (int i = 0; i < n; i++) out[i] *= inv;
}

__global__ void setup_kernel(const int* __restrict__ batch,
                             const float* __restrict__ na, const float* __restrict__ pl,
                             const float* __restrict__ ro, const float* __restrict__ la) {
    int i = blockIdx.x * blockDim.x + threadIdx.x;
    if (i <= GG) {
        int lo = 0, hi = NN;
        while (lo < hi) { int mid = (lo + hi) >> 1; if (batch[mid] < i) lo = mid + 1; else hi = mid; }
        d_gs[i] = lo;
    }
    if (i < NN) { d_kc[i] = 1.f; d_cnt[i] = 0; }
    if (i == 0) {
        for (int l = 0; l < LL; l++) softmax_n(na + l * 4, d_naa + l * 4, 4);
        for (int l = 0; l < LL; l++) softmax_n(pl + l * 3, d_pa + l * 3, 3);
        for (int l = 0; l < LL + 1; l++) softmax_n(ro + l * 3, d_roa + l * 3, 3);
        softmax_n(la, d_laa, 3);
    }
}

__global__ void convert_kernel(const float* __restrict__ x, const float* __restrict__ W) {
    int idx = blockIdx.x * blockDim.x + threadIdx.x;
    if (idx < NHTOT) {
        float v = x[idx];
        __nv_bfloat16 h = __float2bfloat16(v);
        d_hhi[idx] = h;
        d_hlo[idx] = __float2bfloat16(v - __bfloat162float(h));
    } else if (idx < NHTOT + HSQ) {
        int i = idx - NHTOT;
        int k = i >> 7, n = i & 127;
        float v = W[k * HH + n];
        __nv_bfloat16 h = __float2bfloat16(v);
        d_B1hi[n * HH + k] = h;
        d_B1lo[n * HH + k] = __float2bfloat16(v - __bfloat162float(h));
    }
}

__global__ void csr_count(const int* __restrict__ ei) {
    int e = blockIdx.x * blockDim.x + threadIdx.x;
    if (e >= EE) return;
    atomicAdd(&d_cnt[ei[EE + e]], 1);
}

__global__ void scan1() {
    __shared__ int sh[256];
    int i = blockIdx.x * 256 + threadIdx.x;
    int v = (i < NN) ? d_cnt[i] : 0;
    sh[threadIdx.x] = v;
    __syncthreads();
#pragma unroll
    for (int d = 1; d < 256; d <<= 1) {
        int t = (threadIdx.x >= d) ? sh[threadIdx.x - d] : 0;
        __syncthreads();
        sh[threadIdx.x] += t;
        __syncthreads();
    }
    if (i < NN) d_rp[i + 1] = sh[threadIdx.x];
    if (threadIdx.x == 255) d_bsum[blockIdx.x] = sh[255];
}

__global__ void scan2() {
    __shared__ int sh[256];
    int t = threadIdx.x;
    int v = (t < NB) ? d_bsum[t] : 0;
    sh[t] = v;
    __syncthreads();
#pragma unroll
    for (int d = 1; d < 256; d <<= 1) {
        int tv = (t >= d) ? sh[t - d] : 0;
        __syncthreads();
        sh[t] += tv;
        __syncthreads();
    }
    if (t < NB) d_bsum[t] = sh[t] - v;
}

__global__ void scan3() {
    int i = blockIdx.x * 256 + threadIdx.x;
    if (i < NN) d_rp[i + 1] += d_bsum[blockIdx.x];
    if (i == 0) d_rp[0] = 0;
}

__global__ void csr_fill(const int* __restrict__ ei) {
    int e = blockIdx.x * blockDim.x + threadIdx.x;
    if (e >= EE) return;
    int d = ei[EE + e];
    int old = atomicSub(&d_cnt[d], 1);
    d_colsrc[d_rp[d] + old - 1] = ei[e];
}

// combine_W (idx < 4*HSQ) + deg (idx - 4*HSQ < NN) + stats zero, one kernel
__global__ void combine_deg(const float* __restrict__ W, const float* __restrict__ na) {
    int idx = blockIdx.x * blockDim.x + threadIdx.x;
    if (idx == 0) { d_stats[0] = 0.0; d_stats[1] = 0.0; }
    if (idx < 4 * HSQ) {
        int k = idx >> 7, n = idx & 127;
        int p = k >> 7, kk = k & 127;
        int widx = kk * HH + n;
        float a0 = na[0], a1 = na[1], a2 = na[2], a3 = na[3];
        float v;
        if (p == 0)      v = a1 * W[2 * HSQ + widx] + a2 * W[3 * HSQ + widx] + a3 * W[4 * HSQ + widx];
        else if (p == 1) v = a2 * W[3 * HSQ + widx];  // x s_agg (sage-neigh via acc2 path uses p==2)
        else if (p == 2) v = a1 * W[1 * HSQ + widx];  // x s_agg (separate acc, rdeg epilogue)
        else             v = a0 * W[widx];            // x g_agg
        if (p == 1) v += a3 * W[5 * HSQ + widx];      // gconv neighbor term
        __nv_bfloat16 h = __float2bfloat16(v);
        d_Bchi[(size_t)n * KBIG + k] = h;
        d_Bclo[(size_t)n * KBIG + k] = __float2bfloat16(v - __bfloat162float(h));
    } else {
        int n = idx - 4 * HSQ;
        if (n < NN) {
            float kcn = d_kc[n];
            float s = kcn;
            int b = d_rp[n], e = d_rp[n + 1];
            for (int p = b; p < e; p++) s += d_kc[d_colsrc[p]];
            float dg = fmaxf(kcn * s, 1e-6f);
            d_rdeg[n] = 1.f / dg;
            d_rs[n] = rsqrtf(dg);
        }
    }
}

// ---------------- gather aggregation ----------------------------------------
__global__ void aggregate_kernel(const float* __restrict__ h) {
    int gw = (blockIdx.x * blockDim.x + threadIdx.x) >> 5;
    int lane = threadIdx.x & 31;
    if (gw >= NN) return;
    float kcd = d_kc[gw];
    float rsd = d_rs[gw];
    const float4* h4 = (const float4*)h;
    float4 hv = h4[(size_t)gw * 32 + lane];
    float wg = kcd * rsd;
    float4 as = {hv.x * kcd, hv.y * kcd, hv.z * kcd, hv.w * kcd};
    float4 ag = {hv.x * wg, hv.y * wg, hv.z * wg, hv.w * wg};
    int beg = d_rp[gw], end = d_rp[gw + 1];
    for (int p = beg; p < end; p++) {
        int s = d_colsrc[p];
        float w1 = d_kc[s];
        if (w1 != 0.f) {
            float rv = d_rs[s];
            float4 hs = h4[(size_t)s * 32 + lane];
            as.x += hs.x; as.y += hs.y; as.z += hs.z; as.w += hs.w;
            ag.x = fmaf(hs.x, rv, ag.x); ag.y = fmaf(hs.y, rv, ag.y);
            ag.z = fmaf(hs.z, rv, ag.z); ag.w = fmaf(hs.w, rv, ag.w);
        }
    }
    float fg = kcd * rsd;
    as.x *= kcd; as.y *= kcd; as.z *= kcd; as.w *= kcd;
    ag.x *= fg;  ag.y *= fg;  ag.z *= fg;  ag.w *= fg;
    size_t idx = (size_t)gw * HH + lane * 4;
    split_store4(d_shi, d_slo, idx, as);
    split_store4(d_ghi, d_glo, idx, ag);
}

// ---------------- layernorm + gate + pool -----------------------------------
__global__ void gate_kernel(float* __restrict__ h, const float* __restrict__ p0,
                            const float* __restrict__ pa) {
    int gw = (blockIdx.x * blockDim.x + threadIdx.x) >> 5;
    int lane = threadIdx.x & 31;
    if (gw >= NN) return;
    const double invc = 1.0 / ((double)NN * (double)HH);
    double md = d_stats[0] * invc;
    double vd = d_stats[1] * invc - md * md;
    float mean = (float)md;
    float inv = rsqrtf((float)vd + 1e-5f);
    float4 hv = ((const float4*)h)[(size_t)gw * 32 + lane];
    float4 hn;
    hn.x = (hv.x - mean) * inv; hn.y = (hv.y - mean) * inv;
    hn.z = (hv.z - mean) * inv; hn.w = (hv.w - mean) * inv;
    float4 a = ((const float4*)p0)[lane];
    float4 b = ((const float4*)(p0 + HH))[lane];
    float d0 = hn.x * a.x + hn.y * a.y + hn.z * a.z + hn.w * a.w;
    float d1 = hn.x * b.x + hn.y * b.y + hn.z * b.z + hn.w * b.w;
#pragma unroll
    for (int o = 16; o; o >>= 1) {
        d0 += __shfl_xor_sync(0xffffffffu, d0, o);
        d1 += __shfl_xor_sync(0xffffffffu, d1, o);
    }
    float g1 = 1.f / (1.f + expf(-d0));
    float g2 = tanhf(d1);
    float gate = pa[0] * g1 + pa[1] * g2 + pa[2];
    float kv = gate > 0.01f ? 1.f : 0.f;
    float sc = gate * kv;
    hn.x *= sc; hn.y *= sc; hn.z *= sc; hn.w *= sc;
    ((float4*)h)[(size_t)gw * 32 + lane] = hn;
    size_t idx = (size_t)gw * HH + lane * 4;
    split_store4(d_hhi, d_hlo, idx, hn);
    if (lane == 0) d_kc[gw] *= kv;
}

// ---------------- readout ----------------------------------------------------
__global__ void readout_kernel(const float* __restrict__ h, int r) {
    int g = blockIdx.x, k = threadIdx.x;
    int b = d_gs[g], e = d_gs[g + 1];
    float s = 0.f, mx = -INFINITY;
    for (int n = b; n < e; n++) {
        float v = h[(size_t)n * HH + k];
        s += v;
        mx = fmaxf(mx, v);
    }
    float c = (float)(e - b);
    float mean = s / fmaxf(c, 1.f);
    if (e == b) mx = 0.f;
    const float* w = d_roa + r * 3;
    d_reps[((size_t)r * GG + g) * HH + k] = w[0] * mean + w[1] * mx + w[2] * s;
}

// ---------------- final head -------------------------------------------------
__global__ void final_head(const float* __restrict__ Wo, const float* __restrict__ bo,
                           const float* __restrict__ Wc, const float* __restrict__ bc,
                           float* __restrict__ out) {
    __shared__ float zr[HH];
    __shared__ float z2[HH];
    __shared__ float lg[OUTC];
    __shared__ float s_lse;
    int g = blockIdx.x, k = threadIdx.x;
    int idx = g * HH + k;
    float r0 = d_reps[idx];
    float r1 = d_reps[GG * HH + idx];
    float r2 = d_reps[2 * GG * HH + idx];
    float r3 = d_reps[3 * GG * HH + idx];
    float s = r0 + r1 + r2 + r3;
    float mx = fmaxf(fmaxf(r0, r1), fmaxf(r2, r3));
    zr[k] = d_laa[0] * eluf(s) + d_laa[1] * eluf(s * 0.25f) + d_laa[2] * eluf(mx);
    __syncthreads();
    float acc = bo[k];
    for (int k2 = 0; k2 < HH; k2++) acc = fmaf(zr[k2], Wo[k2 * HH + k], acc);
    z2[k] = eluf(acc);
    __syncthreads();
    if (k < OUTC) {
        float accl = bc[k];
        for (int k2 = 0; k2 < HH; k2++) accl = fmaf(z2[k2], Wc[k2 * OUTC + k], accl);
        lg[k] = accl;
    }
    __syncthreads();
    if (k == 0) {
        float m = lg[0];
        for (int i = 1; i < OUTC; i++) m = fmaxf(m, lg[i]);
        float se = 0.f;
        for (int i = 0; i < OUTC; i++) se += expf(lg[i] - m);
        s_lse = m + logf(se);
    }
    __syncthreads();
    if (k < OUTC) out[g * OUTC + k] = lg[k] - s_lse;
}

// ---------------- launch ------------------------------------------------------
extern "C" void kernel_launch(void* const* d_in, const int* in_sizes, int n_in,
                              void* d_out, int out_size) {
    const float* x         = (const float*)d_in[0];
    const int*   ei        = (const int*)d_in[1];
    const int*   batch     = (const int*)d_in[2];
    const float* lin1_W    = (const float*)d_in[3];
    const float* lin1_b    = (const float*)d_in[4];
    const float* gnn_W     = (const float*)d_in[5];
    const float* pool_p    = (const float*)d_in[6];
    const float* lin_out_W = (const float*)d_in[7];
    const float* lin_out_b = (const float*)d_in[8];
    const float* cls_W     = (const float*)d_in[9];
    const float* cls_b     = (const float*)d_in[10];
    const float* na_log    = (const float*)d_in[11];
    const float* pool_log  = (const float*)d_in[12];
    const float* ro_log    = (const float*)d_in[13];
    const float* la_log    = (const float*)d_in[14];
    float* out = (float*)d_out;

    float *bufA, *bufB, *naa, *pa, *rdeg;
    __nv_bfloat16 *hhi, *hlo, *shi, *slo, *ghi, *glo;
    __nv_bfloat16 *Bchi, *Bclo, *B1hi, *B1lo;
    cudaGetSymbolAddress((void**)&bufA, d_bufA);
    cudaGetSymbolAddress((void**)&bufB, d_bufB);
    cudaGetSymbolAddress((void**)&naa, d_naa);
    cudaGetSymbolAddress((void**)&pa, d_pa);
    cudaGetSymbolAddress((void**)&rdeg, d_rdeg);
    cudaGetSymbolAddress((void**)&hhi, d_hhi);
    cudaGetSymbolAddress((void**)&hlo, d_hlo);
    cudaGetSymbolAddress((void**)&shi, d_shi);
    cudaGetSymbolAddress((void**)&slo, d_slo);
    cudaGetSymbolAddress((void**)&ghi, d_ghi);
    cudaGetSymbolAddress((void**)&glo, d_glo);
    cudaGetSymbolAddress((void**)&Bchi, d_Bchi);
    cudaGetSymbolAddress((void**)&Bclo, d_Bclo);
    cudaGetSymbolAddress((void**)&B1hi, d_B1hi);
    cudaGetSymbolAddress((void**)&B1lo, d_B1lo);

    cudaFuncSetAttribute(gemm_mma<2, 0>, cudaFuncAttributeMaxDynamicSharedMemorySize, SM_TOTAL);
    cudaFuncSetAttribute(gemm_mma<8, 1>, cudaFuncAttributeMaxDynamicSharedMemorySize, SM_TOTAL);

    const int GB = (NN + 127) / 128;
    const int EB = (EE + 255) / 256;
    const int WB = (NN * 32 + 255) / 256;
    const int NBK = (NN + 255) / 256;

    // 1: setup (graph starts + softmaxes + kc/cnt init)
    setup_kernel<<<NBK, 256>>>(batch, na_log, pool_log, ro_log, la_log);
    // 2: conversions
    convert_kernel<<<(NHTOT + HSQ + 255) / 256, 256>>>(x, lin1_W);
    // 3: csr count
    csr_count<<<EB, 256>>>(ei);
    // 4: lin1 GEMM  <-- profiled slot
    gemm_mma<2, 0><<<GB, 256, SM_TOTAL>>>(hhi, hlo, hhi, hlo, hhi, hlo,
                                          B1hi, B1lo, bufA, hhi, hlo, lin1_b, nullptr);
    scan1<<<NBK, 256>>>();
    scan2<<<1, 256>>>();
    scan3<<<NBK, 256>>>();
    csr_fill<<<EB, 256>>>(ei);
    readout_kernel<<<GG, HH>>>(bufA, 0);

    float* hcur = bufA;
    float* hnew = bufB;
    for (int i = 0; i < LL; i++) {
        const float* Wi = gnn_W + (size_t)i * 6 * HSQ;
        combine_deg<<<(4 * HSQ + NN + 255) / 256, 256>>>(Wi, naa + i * 4);
        aggregate_kernel<<<WB, 256>>>(hcur);
        gemm_mma<8, 1><<<GB, 256, SM_TOTAL>>>(hhi, hlo, shi, slo, ghi, glo,
                                              Bchi, Bclo, hnew, nullptr, nullptr,
                                              nullptr, rdeg);
        gate_kernel<<<WB, 256>>>(hnew, pool_p + (size_t)i * 2 * HH, pa + i * 3);
        readout_kernel<<<GG, HH>>>(hnew, i + 1);
        float* t = hcur; hcur = hnew; hnew = t;
    }

    final_head<<<GG, HH>>>(lin_out_W, lin_out_b, cls_W, cls_b, out);
}

// round 7
// speedup vs baseline: 1.1531x; 1.1531x over previous
#include <cuda_runtime.h>
#include <cuda_bf16.h>
#include <math.h>
#include <cstdint>

#define NN 50000
#define EE 800000
#define GG 512
#define HH 128
#define LL 3
#define OUTC 10
#define NHTOT (NN * HH)
#define HSQ (HH * HH)
#define NB ((NN + 255) / 256)
#define KBIG 512
#define NP 50176

// ---------------- scratch (device globals) ----------------------------------
__device__ float  d_bufA[NHTOT];
__device__ float  d_bufB[NHTOT];
__device__ float  d_kc[NN];
__device__ float  d_rs[NN];
__device__ float  d_rdeg[NN];
__device__ int    d_rp[NN + 1];
__device__ int    d_cnt[NN];
__device__ int    d_bsum[NB];
__device__ int    d_colsrc[EE];
__device__ float  d_reps[(LL + 1) * GG * HH];
__device__ __nv_bfloat16 d_hhi[NP * HH], d_hlo[NP * HH];     // h (or x) split
__device__ __nv_bfloat16 d_shi[NP * HH], d_slo[NP * HH];     // s_agg split
__device__ __nv_bfloat16 d_srhi[NP * HH], d_srlo[NP * HH];   // s_agg*rdeg split
__device__ __nv_bfloat16 d_ghi[NP * HH], d_glo[NP * HH];     // g_agg split
__device__ __nv_bfloat16 d_Bchi[KBIG * HH];                  // combined B [n][k] hi
__device__ __nv_bfloat16 d_Bclo[KBIG * HH];
__device__ __nv_bfloat16 d_B1hi[HSQ];
__device__ __nv_bfloat16 d_B1lo[HSQ];
__device__ int    d_gs[GG + 1];
__device__ float  d_naa[LL * 4];
__device__ float  d_pa[LL * 3];
__device__ float  d_roa[(LL + 1) * 3];
__device__ float  d_laa[3];
__device__ double d_stats[2];

__device__ __forceinline__ float eluf(float x) { return x > 0.f ? x : expm1f(x); }

__device__ __forceinline__ uint32_t smem_u32(const void* p) {
    uint32_t a;
    asm("{ .reg .u64 t; cvta.to.shared.u64 t, %1; cvt.u32.u64 %0, t; }" : "=r"(a) : "l"(p));
    return a;
}

__device__ __forceinline__ void ldm_x4(uint32_t r[4], uint32_t addr) {
    asm volatile("ldmatrix.sync.aligned.m8n8.x4.shared.b16 {%0,%1,%2,%3}, [%4];"
                 : "=r"(r[0]), "=r"(r[1]), "=r"(r[2]), "=r"(r[3]) : "r"(addr));
}

__device__ __forceinline__ void mma_bf16(float c[4], const uint32_t a[4],
                                         uint32_t b0, uint32_t b1) {
    asm volatile(
        "mma.sync.aligned.m16n8k16.row.col.f32.bf16.bf16.f32 "
        "{%0,%1,%2,%3},{%4,%5,%6,%7},{%8,%9},{%0,%1,%2,%3};"
        : "+f"(c[0]), "+f"(c[1]), "+f"(c[2]), "+f"(c[3])
        : "r"(a[0]), "r"(a[1]), "r"(a[2]), "r"(a[3]), "r"(b0), "r"(b1));
}

#define CP_ASYNC16(dst, src) asm volatile("cp.async.cg.shared.global [%0], [%1], 16;" :: "r"(dst), "l"(src))
#define CP_COMMIT()          asm volatile("cp.async.commit_group;")
#define CP_WAIT(n)           asm volatile("cp.async.wait_group %0;" :: "n"(n))

// 64B-row smem tile (32 bf16/row), XOR swizzle: conflict-free ldmatrix
__device__ __forceinline__ uint32_t swz32(int row, int col) {
    return (uint32_t)(row * 64 + ((((col >> 3) ^ ((row >> 1) & 3))) << 4));
}

__device__ __forceinline__ void split_store4(__nv_bfloat16* hi, __nv_bfloat16* lo,
                                             size_t idx, float4 v) {
    __nv_bfloat162 h0 = __floats2bfloat162_rn(v.x, v.y);
    __nv_bfloat162 h1 = __floats2bfloat162_rn(v.z, v.w);
    float2 f0 = __bfloat1622float2(h0), f1 = __bfloat1622float2(h1);
    *(__nv_bfloat162*)&hi[idx]     = h0;
    *(__nv_bfloat162*)&hi[idx + 2] = h1;
    *(__nv_bfloat162*)&lo[idx]     = __floats2bfloat162_rn(v.x - f0.x, v.y - f0.y);
    *(__nv_bfloat162*)&lo[idx + 2] = __floats2bfloat162_rn(v.z - f1.x, v.w - f1.y);
}

// stage: AHI(8K) ALO(8K) BHI(8K) BLO(8K) = 32KB; 3 stages = 96KB
#define STG_SZ   32768
#define OFF_ALO  8192
#define OFF_BHI  16384
#define OFF_BLO  24576
#define SM_TOTAL 98304

__device__ __forceinline__ void load_stage(
    uint32_t base, const __nv_bfloat16* ah, const __nv_bfloat16* al,
    const __nv_bfloat16* bh, const __nv_bfloat16* bl, int lrow, int lcol) {
#pragma unroll
    for (int j = 0; j < 2; j++) {
        int colbf = lcol + j * 8;
        uint32_t d = swz32(lrow, colbf);
        CP_ASYNC16(base + d,           ah + colbf);
        CP_ASYNC16(base + OFF_ALO + d, al + colbf);
        CP_ASYNC16(base + OFF_BHI + d, bh + colbf);
        CP_ASYNC16(base + OFF_BLO + d, bl + colbf);
    }
    CP_COMMIT();
}

__device__ __forceinline__ void compute_slice(float (&acc)[4][4][4], uint32_t base,
                                              int m_base, int n_base, int lane) {
    int lr = lane & 15, lg2 = (lane >> 4) * 8;
#pragma unroll
    for (int ks = 0; ks < 2; ks++) {
        int k0 = ks * 16;
        uint32_t bhm[2][4], blm[2][4];
#pragma unroll
        for (int np = 0; np < 2; np++) {
            int row = n_base + np * 16 + lr;
            ldm_x4(bhm[np], base + OFF_BHI + swz32(row, k0 + lg2));
            ldm_x4(blm[np], base + OFF_BLO + swz32(row, k0 + lg2));
        }
#pragma unroll
        for (int mt = 0; mt < 4; mt++) {
            int row = m_base + mt * 16 + lr;
            uint32_t ah[4], al[4];
            ldm_x4(ah, base + swz32(row, k0 + lg2));
            ldm_x4(al, base + OFF_ALO + swz32(row, k0 + lg2));
#pragma unroll
            for (int nt = 0; nt < 4; nt++) {
                int np = nt >> 1, sel = nt & 1;
                uint32_t b0h = sel ? bhm[np][1] : bhm[np][0];
                uint32_t b1h = sel ? bhm[np][3] : bhm[np][2];
                uint32_t b0l = sel ? blm[np][1] : blm[np][0];
                uint32_t b1l = sel ? blm[np][3] : blm[np][2];
                mma_bf16(acc[mt][nt], ah, b0h, b1h);
                mma_bf16(acc[mt][nt], al, b0h, b1h);
                mma_bf16(acc[mt][nt], ah, b0l, b1l);
            }
        }
    }
}

// ---------------- tensor-core GEMM ------------------------------------------
// NSLICES = K/32. chunk = slice>>2: 0->a0(h), 1->a1(s), 2->a2(sr), 3->a3(g)
// MODE 0: bias+elu, writes C + split Chi/Clo    MODE 1: elu + LN stats
template <int NSLICES, int MODE>
__global__ void __launch_bounds__(256, 2) gemm_mma(
    const __nv_bfloat16* __restrict__ a0h, const __nv_bfloat16* __restrict__ a0l,
    const __nv_bfloat16* __restrict__ a1h, const __nv_bfloat16* __restrict__ a1l,
    const __nv_bfloat16* __restrict__ a2h, const __nv_bfloat16* __restrict__ a2l,
    const __nv_bfloat16* __restrict__ a3h, const __nv_bfloat16* __restrict__ a3l,
    const __nv_bfloat16* __restrict__ Bh, const __nv_bfloat16* __restrict__ Bl,
    float* __restrict__ C, __nv_bfloat16* __restrict__ Chi, __nv_bfloat16* __restrict__ Clo,
    const float* __restrict__ bias) {
    extern __shared__ char smem[];
    uint32_t sb = smem_u32(smem);
    const int tid = threadIdx.x;
    const int wid = tid >> 5, lane = tid & 31;
    const int warp_m = wid & 1, warp_n = wid >> 1;
    const int bm = blockIdx.x * 128;
    const int KB = NSLICES * 32;

    const int lrow = tid >> 1;
    const int lcol = (tid & 1) * 16;
    const size_t arow = (size_t)(bm + lrow) * HH;
    const size_t brow = (size_t)lrow * KB;

    float acc[4][4][4];
#pragma unroll
    for (int i = 0; i < 4; i++)
#pragma unroll
        for (int j = 0; j < 4; j++)
#pragma unroll
            for (int q = 0; q < 4; q++) acc[i][j][q] = 0.f;

    const int m_base = warp_m * 64;
    const int n_base = warp_n * 32;

#pragma unroll
    for (int pf = 0; pf < 2; pf++) {
        const int chunk = pf >> 2, koff = (pf & 3) * 32;
        const __nv_bfloat16* ah = (chunk == 0) ? a0h : (chunk == 1) ? a1h : (chunk == 2) ? a2h : a3h;
        const __nv_bfloat16* al = (chunk == 0) ? a0l : (chunk == 1) ? a1l : (chunk == 2) ? a2l : a3l;
        load_stage(sb + pf * STG_SZ, ah + arow + koff, al + arow + koff,
                   Bh + brow + pf * 32, Bl + brow + pf * 32, lrow, lcol);
    }

#pragma unroll
    for (int s = 0; s < NSLICES; s++) {
        if (s + 2 < NSLICES) {
            const int sn = s + 2;
            const int chunk = sn >> 2, koff = (sn & 3) * 32;
            const __nv_bfloat16* ah = (chunk == 0) ? a0h : (chunk == 1) ? a1h : (chunk == 2) ? a2h : a3h;
            const __nv_bfloat16* al = (chunk == 0) ? a0l : (chunk == 1) ? a1l : (chunk == 2) ? a2l : a3l;
            load_stage(sb + (sn % 3) * STG_SZ, ah + arow + koff, al + arow + koff,
                       Bh + brow + sn * 32, Bl + brow + sn * 32, lrow, lcol);
            CP_WAIT(2);
        } else if (s + 2 == NSLICES) {
            CP_WAIT(1);
        } else {
            CP_WAIT(0);
        }
        __syncthreads();
        compute_slice(acc, sb + (s % 3) * STG_SZ, m_base, n_base, lane);
        __syncthreads();
    }

    // ---- epilogue
    float lsum = 0.f, lsq = 0.f;
    int rq = lane >> 2, cq = (lane & 3) * 2;
#pragma unroll
    for (int mt = 0; mt < 4; mt++) {
#pragma unroll
        for (int half = 0; half < 2; half++) {
            int gm = bm + m_base + mt * 16 + rq + half * 8;
            if (gm >= NN) continue;
#pragma unroll
            for (int nt = 0; nt < 4; nt++) {
                int col = n_base + nt * 8 + cq;
                float v0 = acc[mt][nt][half * 2];
                float v1 = acc[mt][nt][half * 2 + 1];
                if (MODE == 0) {
                    v0 = eluf(v0 + bias[col]);
                    v1 = eluf(v1 + bias[col + 1]);
                    __nv_bfloat162 h = __floats2bfloat162_rn(v0, v1);
                    float2 hf = __bfloat1622float2(h);
                    *(__nv_bfloat162*)&Chi[(size_t)gm * HH + col] = h;
                    *(__nv_bfloat162*)&Clo[(size_t)gm * HH + col] =
                        __floats2bfloat162_rn(v0 - hf.x, v1 - hf.y);
                } else {
                    v0 = eluf(v0); v1 = eluf(v1);
                    lsum += v0 + v1;
                    lsq = fmaf(v0, v0, lsq); lsq = fmaf(v1, v1, lsq);
                }
                *(float2*)&C[(size_t)gm * HH + col] = make_float2(v0, v1);
            }
        }
    }
    if (MODE == 1) {
        double ds = (double)lsum, dq = (double)lsq;
#pragma unroll
        for (int o = 16; o; o >>= 1) {
            ds += __shfl_down_sync(0xffffffffu, ds, o);
            dq += __shfl_down_sync(0xffffffffu, dq, o);
        }
        __shared__ double ssum[8], ssq[8];
        if (lane == 0) { ssum[wid] = ds; ssq[wid] = dq; }
        __syncthreads();
        if (tid == 0) {
            double a = 0.0, b = 0.0;
#pragma unroll
            for (int i = 0; i < 8; i++) { a += ssum[i]; b += ssq[i]; }
            atomicAdd(&d_stats[0], a);
            atomicAdd(&d_stats[1], b);
        }
    }
}

// ---------------- setup ------------------------------------------------------
__device__ void softmax_n(const float* in, float* out, int n) {
    float m = in[0];
    for (int i = 1; i < n; i++) m = fmaxf(m, in[i]);
    float s = 0.f;
    for (int i = 0; i < n; i++) { out[i] = expf(in[i] - m); s += out[i]; }
    float inv = 1.f / s;
    for (int i = 0; i < n; i++) out[i] *= inv;
}

__global__ void setup_kernel(const int* __restrict__ batch,
                             const float* __restrict__ na, const float* __restrict__ pl,
                             const float* __restrict__ ro, const float* __restrict__ la) {
    int i = blockIdx.x * blockDim.x + threadIdx.x;
    if (i <= GG) {
        int lo = 0, hi = NN;
        while (lo < hi) { int mid = (lo + hi) >> 1; if (batch[mid] < i) lo = mid + 1; else hi = mid; }
        d_gs[i] = lo;
    }
    if (i < NN) { d_kc[i] = 1.f; d_cnt[i] = 0; }
    if (i == 0) {
        for (int l = 0; l < LL; l++) softmax_n(na + l * 4, d_naa + l * 4, 4);
        for (int l = 0; l < LL; l++) softmax_n(pl + l * 3, d_pa + l * 3, 3);
        for (int l = 0; l < LL + 1; l++) softmax_n(ro + l * 3, d_roa + l * 3, 3);
        softmax_n(la, d_laa, 3);
    }
}

__global__ void convert_kernel(const float* __restrict__ x, const float* __restrict__ W) {
    int idx = blockIdx.x * blockDim.x + threadIdx.x;
    if (idx < NHTOT) {
        float v = x[idx];
        __nv_bfloat16 h = __float2bfloat16(v);
        d_hhi[idx] = h;
        d_hlo[idx] = __float2bfloat16(v - __bfloat162float(h));
    } else if (idx < NHTOT + HSQ) {
        int i = idx - NHTOT;
        int k = i >> 7, n = i & 127;
        float v = W[k * HH + n];
        __nv_bfloat16 h = __float2bfloat16(v);
        d_B1hi[n * HH + k] = h;
        d_B1lo[n * HH + k] = __float2bfloat16(v - __bfloat162float(h));
    }
}

__global__ void csr_count(const int* __restrict__ ei) {
    int e = blockIdx.x * blockDim.x + threadIdx.x;
    if (e >= EE) return;
    atomicAdd(&d_cnt[ei[EE + e]], 1);
}

__global__ void scan1() {
    __shared__ int sh[256];
    int i = blockIdx.x * 256 + threadIdx.x;
    int v = (i < NN) ? d_cnt[i] : 0;
    sh[threadIdx.x] = v;
    __syncthreads();
#pragma unroll
    for (int d = 1; d < 256; d <<= 1) {
        int t = (threadIdx.x >= d) ? sh[threadIdx.x - d] : 0;
        __syncthreads();
        sh[threadIdx.x] += t;
        __syncthreads();
    }
    if (i < NN) d_rp[i + 1] = sh[threadIdx.x];
    if (threadIdx.x == 255) d_bsum[blockIdx.x] = sh[255];
}

__global__ void scan2() {
    __shared__ int sh[256];
    int t = threadIdx.x;
    int v = (t < NB) ? d_bsum[t] : 0;
    sh[t] = v;
    __syncthreads();
#pragma unroll
    for (int d = 1; d < 256; d <<= 1) {
        int tv = (t >= d) ? sh[t - d] : 0;
        __syncthreads();
        sh[t] += tv;
        __syncthreads();
    }
    if (t < NB) d_bsum[t] = sh[t] - v;
}

__global__ void scan3() {
    int i = blockIdx.x * 256 + threadIdx.x;
    if (i < NN) d_rp[i + 1] += d_bsum[blockIdx.x];
    if (i == 0) d_rp[0] = 0;
}

__global__ void csr_fill(const int* __restrict__ ei) {
    int e = blockIdx.x * blockDim.x + threadIdx.x;
    if (e >= EE) return;
    int d = ei[EE + e];
    int old = atomicSub(&d_cnt[d], 1);
    d_colsrc[d_rp[d] + old - 1] = ei[e];
}

// combine_W + deg + stats zero
__global__ void combine_deg(const float* __restrict__ W, const float* __restrict__ na) {
    int idx = blockIdx.x * blockDim.x + threadIdx.x;
    if (idx == 0) { d_stats[0] = 0.0; d_stats[1] = 0.0; }
    if (idx < 4 * HSQ) {
        int k = idx >> 7, n = idx & 127;
        int p = k >> 7, kk = k & 127;
        int widx = kk * HH + n;
        float a0 = na[0], a1 = na[1], a2 = na[2], a3 = na[3];
        float v;
        if (p == 0)      v = a1 * W[2 * HSQ + widx] + a2 * W[3 * HSQ + widx] + a3 * W[4 * HSQ + widx];
        else if (p == 1) v = a2 * W[3 * HSQ + widx] + a3 * W[5 * HSQ + widx];  // x s_agg
        else if (p == 2) v = a1 * W[1 * HSQ + widx];                            // x s_agg*rdeg
        else             v = a0 * W[widx];                                      // x g_agg
        __nv_bfloat16 h = __float2bfloat16(v);
        d_Bchi[(size_t)n * KBIG + k] = h;
        d_Bclo[(size_t)n * KBIG + k] = __float2bfloat16(v - __bfloat162float(h));
    } else {
        int n = idx - 4 * HSQ;
        if (n < NN) {
            float kcn = d_kc[n];
            float s = kcn;
            int b = d_rp[n], e = d_rp[n + 1];
            for (int p = b; p < e; p++) s += d_kc[d_colsrc[p]];
            float dg = fmaxf(kcn * s, 1e-6f);
            d_rdeg[n] = 1.f / dg;
            d_rs[n] = rsqrtf(dg);
        }
    }
}

// ---------------- gather aggregation ----------------------------------------
__global__ void aggregate_kernel(const float* __restrict__ h) {
    int gw = (blockIdx.x * blockDim.x + threadIdx.x) >> 5;
    int lane = threadIdx.x & 31;
    if (gw >= NN) return;
    float kcd = d_kc[gw];
    float rsd = d_rs[gw];
    float rdg = d_rdeg[gw];
    const float4* h4 = (const float4*)h;
    float4 hv = h4[(size_t)gw * 32 + lane];
    float wg = kcd * rsd;
    float4 as = {hv.x * kcd, hv.y * kcd, hv.z * kcd, hv.w * kcd};
    float4 ag = {hv.x * wg, hv.y * wg, hv.z * wg, hv.w * wg};
    int beg = d_rp[gw], end = d_rp[gw + 1];
    for (int p = beg; p < end; p++) {
        int s = d_colsrc[p];
        float w1 = d_kc[s];
        if (w1 != 0.f) {
            float rv = d_rs[s];
            float4 hs = h4[(size_t)s * 32 + lane];
            as.x += hs.x; as.y += hs.y; as.z += hs.z; as.w += hs.w;
            ag.x = fmaf(hs.x, rv, ag.x); ag.y = fmaf(hs.y, rv, ag.y);
            ag.z = fmaf(hs.z, rv, ag.z); ag.w = fmaf(hs.w, rv, ag.w);
        }
    }
    float fg = kcd * rsd;
    as.x *= kcd; as.y *= kcd; as.z *= kcd; as.w *= kcd;
    ag.x *= fg;  ag.y *= fg;  ag.z *= fg;  ag.w *= fg;
    float4 asr = {as.x * rdg, as.y * rdg, as.z * rdg, as.w * rdg};
    size_t idx = (size_t)gw * HH + lane * 4;
    split_store4(d_shi, d_slo, idx, as);
    split_store4(d_srhi, d_srlo, idx, asr);
    split_store4(d_ghi, d_glo, idx, ag);
}

// ---------------- layernorm + gate + pool -----------------------------------
__global__ void gate_kernel(float* __restrict__ h, const float* __restrict__ p0,
                            const float* __restrict__ pa) {
    int gw = (blockIdx.x * blockDim.x + threadIdx.x) >> 5;
    int lane = threadIdx.x & 31;
    if (gw >= NN) return;
    const double invc = 1.0 / ((double)NN * (double)HH);
    double md = d_stats[0] * invc;
    double vd = d_stats[1] * invc - md * md;
    float mean = (float)md;
    float inv = rsqrtf((float)vd + 1e-5f);
    float4 hv = ((const float4*)h)[(size_t)gw * 32 + lane];
    float4 hn;
    hn.x = (hv.x - mean) * inv; hn.y = (hv.y - mean) * inv;
    hn.z = (hv.z - mean) * inv; hn.w = (hv.w - mean) * inv;
    float4 a = ((const float4*)p0)[lane];
    float4 b = ((const float4*)(p0 + HH))[lane];
    float d0 = hn.x * a.x + hn.y * a.y + hn.z * a.z + hn.w * a.w;
    float d1 = hn.x * b.x + hn.y * b.y + hn.z * b.z + hn.w * b.w;
#pragma unroll
    for (int o = 16; o; o >>= 1) {
        d0 += __shfl_xor_sync(0xffffffffu, d0, o);
        d1 += __shfl_xor_sync(0xffffffffu, d1, o);
    }
    float g1 = 1.f / (1.f + expf(-d0));
    float g2 = tanhf(d1);
    float gate = pa[0] * g1 + pa[1] * g2 + pa[2];
    float kv = gate > 0.01f ? 1.f : 0.f;
    float sc = gate * kv;
    hn.x *= sc; hn.y *= sc; hn.z *= sc; hn.w *= sc;
    ((float4*)h)[(size_t)gw * 32 + lane] = hn;
    size_t idx = (size_t)gw * HH + lane * 4;
    split_store4(d_hhi, d_hlo, idx, hn);
    if (lane == 0) d_kc[gw] *= kv;
}

// ---------------- readout ----------------------------------------------------
__global__ void readout_kernel(const float* __restrict__ h, int r) {
    int g = blockIdx.x, k = threadIdx.x;
    int b = d_gs[g], e = d_gs[g + 1];
    float s = 0.f, mx = -INFINITY;
    for (int n = b; n < e; n++) {
        float v = h[(size_t)n * HH + k];
        s += v;
        mx = fmaxf(mx, v);
    }
    float c = (float)(e - b);
    float mean = s / fmaxf(c, 1.f);
    if (e == b) mx = 0.f;
    const float* w = d_roa + r * 3;
    d_reps[((size_t)r * GG + g) * HH + k] = w[0] * mean + w[1] * mx + w[2] * s;
}

// ---------------- final head -------------------------------------------------
__global__ void final_head(const float* __restrict__ Wo, const float* __restrict__ bo,
                           const float* __restrict__ Wc, const float* __restrict__ bc,
                           float* __restrict__ out) {
    __shared__ float zr[HH];
    __shared__ float z2[HH];
    __shared__ float lg[OUTC];
    __shared__ float s_lse;
    int g = blockIdx.x, k = threadIdx.x;
    int idx = g * HH + k;
    float r0 = d_reps[idx];
    float r1 = d_reps[GG * HH + idx];
    float r2 = d_reps[2 * GG * HH + idx];
    float r3 = d_reps[3 * GG * HH + idx];
    float s = r0 + r1 + r2 + r3;
    float mx = fmaxf(fmaxf(r0, r1), fmaxf(r2, r3));
    zr[k] = d_laa[0] * eluf(s) + d_laa[1] * eluf(s * 0.25f) + d_laa[2] * eluf(mx);
    __syncthreads();
    float acc = bo[k];
    for (int k2 = 0; k2 < HH; k2++) acc = fmaf(zr[k2], Wo[k2 * HH + k], acc);
    z2[k] = eluf(acc);
    __syncthreads();
    if (k < OUTC) {
        float accl = bc[k];
        for (int k2 = 0; k2 < HH; k2++) accl = fmaf(z2[k2], Wc[k2 * OUTC + k], accl);
        lg[k] = accl;
    }
    __syncthreads();
    if (k == 0) {
        float m = lg[0];
        for (int i = 1; i < OUTC; i++) m = fmaxf(m, lg[i]);
        float se = 0.f;
        for (int i = 0; i < OUTC; i++) se += expf(lg[i] - m);
        s_lse = m + logf(se);
    }
    __syncthreads();
    if (k < OUTC) out[g * OUTC + k] = lg[k] - s_lse;
}

// ---------------- launch ------------------------------------------------------
extern "C" void kernel_launch(void* const* d_in, const int* in_sizes, int n_in,
                              void* d_out, int out_size) {
    const float* x         = (const float*)d_in[0];
    const int*   ei        = (const int*)d_in[1];
    const int*   batch     = (const int*)d_in[2];
    const float* lin1_W    = (const float*)d_in[3];
    const float* lin1_b    = (const float*)d_in[4];
    const float* gnn_W     = (const float*)d_in[5];
    const float* pool_p    = (const float*)d_in[6];
    const float* lin_out_W = (const float*)d_in[7];
    const float* lin_out_b = (const float*)d_in[8];
    const float* cls_W     = (const float*)d_in[9];
    const float* cls_b     = (const float*)d_in[10];
    const float* na_log    = (const float*)d_in[11];
    const float* pool_log  = (const float*)d_in[12];
    const float* ro_log    = (const float*)d_in[13];
    const float* la_log    = (const float*)d_in[14];
    float* out = (float*)d_out;

    float *bufA, *bufB, *naa, *pa;
    __nv_bfloat16 *hhi, *hlo, *shi, *slo, *srhi, *srlo, *ghi, *glo;
    __nv_bfloat16 *Bchi, *Bclo, *B1hi, *B1lo;
    cudaGetSymbolAddress((void**)&bufA, d_bufA);
    cudaGetSymbolAddress((void**)&bufB, d_bufB);
    cudaGetSymbolAddress((void**)&naa, d_naa);
    cudaGetSymbolAddress((void**)&pa, d_pa);
    cudaGetSymbolAddress((void**)&hhi, d_hhi);
    cudaGetSymbolAddress((void**)&hlo, d_hlo);
    cudaGetSymbolAddress((void**)&shi, d_shi);
    cudaGetSymbolAddress((void**)&slo, d_slo);
    cudaGetSymbolAddress((void**)&srhi, d_srhi);
    cudaGetSymbolAddress((void**)&srlo, d_srlo);
    cudaGetSymbolAddress((void**)&ghi, d_ghi);
    cudaGetSymbolAddress((void**)&glo, d_glo);
    cudaGetSymbolAddress((void**)&Bchi, d_Bchi);
    cudaGetSymbolAddress((void**)&Bclo, d_Bclo);
    cudaGetSymbolAddress((void**)&B1hi, d_B1hi);
    cudaGetSymbolAddress((void**)&B1lo, d_B1lo);

    cudaFuncSetAttribute(gemm_mma<4, 0>, cudaFuncAttributeMaxDynamicSharedMemorySize, SM_TOTAL);
    cudaFuncSetAttribute(gemm_mma<16, 1>, cudaFuncAttributeMaxDynamicSharedMemorySize, SM_TOTAL);

    const int GB = (NN + 127) / 128;
    const int EB = (EE + 255) / 256;
    const int WB = (NN * 32 + 255) / 256;
    const int NBK = (NN + 255) / 256;

    setup_kernel<<<NBK, 256>>>(batch, na_log, pool_log, ro_log, la_log);
    convert_kernel<<<(NHTOT + HSQ + 255) / 256, 256>>>(x, lin1_W);
    csr_count<<<EB, 256>>>(ei);
    // launch #4 = profiled slot: lin1 GEMM
    gemm_mma<4, 0><<<GB, 256, SM_TOTAL>>>(hhi, hlo, hhi, hlo, hhi, hlo, hhi, hlo,
                                          B1hi, B1lo, bufA, hhi, hlo, lin1_b);
    scan1<<<NBK, 256>>>();
    scan2<<<1, 256>>>();
    scan3<<<NBK, 256>>>();
    csr_fill<<<EB, 256>>>(ei);
    readout_kernel<<<GG, HH>>>(bufA, 0);

    float* hcur = bufA;
    float* hnew = bufB;
    for (int i = 0; i < LL; i++) {
        const float* Wi = gnn_W + (size_t)i * 6 * HSQ;
        combine_deg<<<(4 * HSQ + NN + 255) / 256, 256>>>(Wi, naa + i * 4);
        aggregate_kernel<<<WB, 256>>>(hcur);
        gemm_mma<16, 1><<<GB, 256, SM_TOTAL>>>(hhi, hlo, shi, slo, srhi, srlo, ghi, glo,
                                               Bchi, Bclo, hnew, nullptr, nullptr,
                                               nullptr);
        gate_kernel<<<WB, 256>>>(hnew, pool_p + (size_t)i * 2 * HH, pa + i * 3);
        readout_kernel<<<GG, HH>>>(hnew, i + 1);
        float* t = hcur; hcur = hnew; hnew = t;
    }

    final_head<<<GG, HH>>>(lin_out_W, lin_out_b, cls_W, cls_b, out);
}